// round 10
// baseline (speedup 1.0000x reference)
#include <cuda_runtime.h>
#include <cstdint>
#include <cstddef>

// ===========================================================================
// UNet decoder via warp-level tf32 mma.sync (tensor pipe).
// NOTE: tcgen05 is NOT compilable through this bench (PTX target compute_103
// without the 'a' feature set) — warp MMA is the available tensor path.
// v2: 2-D output tile (4 rows x 32 px) so the A slab (6x34 px x 32ch) is
// loaded once per ic-chunk and reused across all 3 ky taps; vectorized B
// copy; forced 2 CTAs/SM.
// ===========================================================================

__device__ float g_A1[8 * 128 * 128 * 512];  // up2(cat(x,enc3))
__device__ float g_A2[8 * 256 * 256 * 256];  // [conv1out_up | enc2_up]
__device__ float g_A3[8 * 256 * 256 * 128];  // [conv2out | enc1]
__device__ float g_O3[8 * 256 * 256 * 64];   // conv3out
__device__ float g_w1[9 * 512 * 128];        // gw[ky][kx][ic][oc], tf32-rounded
__device__ float g_w2[9 * 256 * 64];
__device__ float g_w3[9 * 128 * 64];
__device__ float g_w4[9 * 64 * 64];          // oc padded 3 -> 64
__device__ float g_s1[8 * 128];
__device__ float g_s2[8 * 64];

__device__ __forceinline__ uint32_t tf32r(float x) {
    uint32_t u;
    asm("cvt.rna.tf32.f32 %0, %1;" : "=r"(u) : "f"(x));
    return u;
}

__device__ __forceinline__ void mma8(float* c, const uint32_t* a, uint32_t b0,
                                     uint32_t b1) {
    asm volatile(
        "mma.sync.aligned.m16n8k8.row.col.f32.tf32.tf32.f32 "
        "{%0,%1,%2,%3}, {%4,%5,%6,%7}, {%8,%9}, {%0,%1,%2,%3};"
        : "+f"(c[0]), "+f"(c[1]), "+f"(c[2]), "+f"(c[3])
        : "r"(a[0]), "r"(a[1]), "r"(a[2]), "r"(a[3]), "r"(b0), "r"(b1));
}

// ---------------------------------------------------------------------------
// NCHW -> NHWC (+ optional nearest 2x upsample). Tile: 64 ch x 64 out-px.
// ---------------------------------------------------------------------------
template <bool UP>
__global__ __launch_bounds__(256) void nchw2nhwc(const float* __restrict__ src,
                                                 float* __restrict__ dst,
                                                 int Csrc, int Hsrc, int Wout,
                                                 int Crow, int coff) {
    constexpr int SXT = UP ? 32 : 64;
    __shared__ float sm[64][SXT + 1];
    const int xtiles = Wout >> 6;
    const int xt = blockIdx.x % xtiles;
    const int ct = blockIdx.x / xtiles;
    const int y = blockIdx.y, b = blockIdx.z;
    const int sy = UP ? (y >> 1) : y;
    const int t = threadIdx.x;

    const float* sp =
        src + ((size_t)(b * Csrc + ct * 64) * Hsrc + sy) * Hsrc + xt * SXT;
    for (int i = t; i < 64 * SXT / 4; i += 256) {
        int c = i / (SXT / 4), q = i % (SXT / 4);
        float4 v = *(const float4*)(sp + (size_t)c * Hsrc * Hsrc + q * 4);
        sm[c][q * 4 + 0] = v.x;
        sm[c][q * 4 + 1] = v.y;
        sm[c][q * 4 + 2] = v.z;
        sm[c][q * 4 + 3] = v.w;
    }
    __syncthreads();
    float* dp = dst + (((size_t)b * Wout + y) * Wout + xt * 64) * Crow + coff +
                ct * 64;
    for (int i = t; i < 1024; i += 256) {
        int x = i >> 4, cq = i & 15;
        int sx = UP ? (x >> 1) : x;
        float4 v = make_float4(sm[cq * 4 + 0][sx], sm[cq * 4 + 1][sx],
                               sm[cq * 4 + 2][sx], sm[cq * 4 + 3][sx]);
        *(float4*)(dp + (size_t)x * Crow + cq * 4) = v;
    }
}

// ---------------------------------------------------------------------------
// Weights: w[oc][ic][ky][kx] -> gw[((ky*3+kx)*IC+ic)*OCp + oc], tf32-rounded.
// ---------------------------------------------------------------------------
__global__ void wtrans(const float* __restrict__ w, float* __restrict__ gw,
                       int OCsrc, int OCp, int IC) {
    int i = blockIdx.x * blockDim.x + threadIdx.x;
    if (i >= 9 * IC * OCp) return;
    int oc = i % OCp;
    int r = i / OCp;
    int ic = r % IC;
    r /= IC;
    int kx = r % 3, ky = r / 3;
    float v = (oc < OCsrc) ? w[((size_t)(oc * IC + ic) * 3 + ky) * 3 + kx] : 0.f;
    gw[i] = __uint_as_float(tf32r(v));
}

__global__ void style_mod(const float* __restrict__ style,
                          const float* __restrict__ fcw,
                          const float* __restrict__ fcb, float* __restrict__ s,
                          int OC) {
    int i = blockIdx.x * blockDim.x + threadIdx.x;
    if (i >= 8 * OC) return;
    int b = i / OC, o = i - b * OC;
    const float* st = style + b * 256;
    const float* wp = fcw + o * 256;
    float a = fcb[o];
#pragma unroll 4
    for (int k = 0; k < 256; k++) a = fmaf(st[k], wp[k], a);
    s[i] = a;
}

// ---------------------------------------------------------------------------
// Implicit-GEMM conv3x3, 2-D tile: CTA = (4 rows x 32 px) x 64 oc.
// M fragment row r = wm*32 + mt*16 + g + h*8  ->  yy = wm, xx = r % 32.
// A slab: 6 rows x 34 px x 32 ch (stride 36), loaded once per ic-chunk.
// B tile: [kx][32 ic][64 oc] (stride 72), reloaded per ky.
// LAYER: 1 512->128 @128^2 (scale,relu, 2x2-dup -> A2 ch0-127)
//        2 256->64  @256^2 (scale,relu -> A3 ch0-63)
//        3 128->64  @256^2 (+fb1,relu -> O3)
//        4  64->64p @256^2 (+fb2, oc<3 -> NCHW out)
// ---------------------------------------------------------------------------
static constexpr int SMEM_A_W = 6 * 34 * 36;              // 7344 words
static constexpr int SMEM_SZ = (SMEM_A_W + 3 * 32 * 72) * 4;  // 57024 B

template <int LAYER>
__global__ __launch_bounds__(256, 2) void conv_mma(
    const float* __restrict__ in, const float* __restrict__ gw,
    const float* __restrict__ sb, float* __restrict__ out) {
    constexpr int H = (LAYER == 1) ? 128 : 256;
    constexpr int W = H;
    constexpr int IC = (LAYER == 1) ? 512 : (LAYER == 2) ? 256
                       : (LAYER == 3) ? 128 : 64;
    constexpr int OCp = (LAYER == 1) ? 128 : 64;  // oc stride in gw
    constexpr int OCB = OCp / 64;
    constexpr int XB = W / 32;

    extern __shared__ __align__(16) uint32_t smem[];
    uint32_t* const sA = smem;                       // [ (ry*34+rx)*36 + c ]
    uint32_t(*const sB)[32][72] =
        (uint32_t(*)[32][72])(smem + SMEM_A_W);      // [kx][ic][oc]

    const int t = threadIdx.x, lane = t & 31, wid = t >> 5;
    const int g = lane >> 2, tig = lane & 3;
    const int wm = wid >> 1, wn = wid & 1;
    const int ty = blockIdx.x / XB, tx = blockIdx.x % XB;
    const int y0 = ty * 4, x0 = tx * 32;
    const int b = blockIdx.y / OCB, ob = (blockIdx.y % OCB) * 64;

    float acc[2][4][4];
#pragma unroll
    for (int mt = 0; mt < 2; mt++)
#pragma unroll
        for (int nt = 0; nt < 4; nt++)
#pragma unroll
            for (int k = 0; k < 4; k++) acc[mt][nt][k] = 0.f;

    const float* inb = in + (size_t)b * H * W * IC;

    for (int ic0 = 0; ic0 < IC; ic0 += 32) {
        __syncthreads();  // prior compute done before overwriting sA/sB
        // ---- A slab: 6 rows x 34 px x 32 ch (zero-padded at borders) ----
        for (int i = t; i < 6 * 34 * 8; i += 256) {
            const int px = i >> 3, q = i & 7;
            const int ry = px / 34, rx = px - ry * 34;
            const int gy = y0 - 1 + ry, gx = x0 - 1 + rx;
            uint4 u = {0u, 0u, 0u, 0u};
            if (gy >= 0 && gy < H && gx >= 0 && gx < W) {
                float4 f = *(const float4*)(inb + ((size_t)gy * W + gx) * IC +
                                            ic0 + q * 4);
                u.x = tf32r(f.x); u.y = tf32r(f.y);
                u.z = tf32r(f.z); u.w = tf32r(f.w);
            }
            *(uint4*)&sA[(size_t)px * 36 + q * 4] = u;
        }
        for (int ky = 0; ky < 3; ky++) {
            if (ky > 0) __syncthreads();  // prev ky compute done before sB overwrite
            // ---- B tile (pre-rounded): vector copy, [kx][ic][oc] ----
            for (int i = t; i < 1536; i += 256) {
                const int oc4 = (i & 15) * 4;
                const int r = i >> 4;
                const int ic = r & 31, kx = r >> 5;
                *(uint4*)&sB[kx][ic][oc4] = *(const uint4*)(
                    gw + (size_t)((ky * 3 + kx) * IC + ic0 + ic) * OCp + ob +
                    oc4);
            }
            __syncthreads();
            const int rowb = (wm + ky) * 34;
#pragma unroll
            for (int kx = 0; kx < 3; kx++) {
#pragma unroll
                for (int ks = 0; ks < 4; ks++) {
                    const int kc = ks * 8;
                    uint32_t a[2][4];
#pragma unroll
                    for (int mt = 0; mt < 2; mt++) {
                        const int p0 = rowb + mt * 16 + g + kx;
                        a[mt][0] = sA[p0 * 36 + kc + tig];
                        a[mt][1] = sA[(p0 + 8) * 36 + kc + tig];
                        a[mt][2] = sA[p0 * 36 + kc + tig + 4];
                        a[mt][3] = sA[(p0 + 8) * 36 + kc + tig + 4];
                    }
#pragma unroll
                    for (int nt = 0; nt < 4; nt++) {
                        const uint32_t b0 = sB[kx][kc + tig][wn * 32 + nt * 8 + g];
                        const uint32_t b1 =
                            sB[kx][kc + tig + 4][wn * 32 + nt * 8 + g];
                        mma8(acc[0][nt], a[0], b0, b1);
                        mma8(acc[1][nt], a[1], b0, b1);
                    }
                }
            }
        }
    }

    // ---------------- epilogue ----------------
    const int y = y0 + wm;
#pragma unroll
    for (int mt = 0; mt < 2; mt++) {
#pragma unroll
        for (int nt = 0; nt < 4; nt++) {
            const int oc = ob + wn * 32 + nt * 8 + tig * 2;
#pragma unroll
            for (int h = 0; h < 2; h++) {
                const int x = x0 + mt * 16 + g + h * 8;
                float v0 = acc[mt][nt][h * 2 + 0];
                float v1 = acc[mt][nt][h * 2 + 1];
                if constexpr (LAYER == 1) {
                    v0 = fmaxf(v0 * sb[b * 128 + oc], 0.f);
                    v1 = fmaxf(v1 * sb[b * 128 + oc + 1], 0.f);
                    float2 pv = make_float2(v0, v1);
#pragma unroll
                    for (int dy = 0; dy < 2; dy++)
#pragma unroll
                        for (int dx = 0; dx < 2; dx++)
                            *(float2*)(out +
                                       (((size_t)b * 256 + 2 * y + dy) * 256 +
                                        2 * x + dx) *
                                           256 +
                                       oc) = pv;
                } else if constexpr (LAYER == 2) {
                    v0 = fmaxf(v0 * sb[b * 64 + oc], 0.f);
                    v1 = fmaxf(v1 * sb[b * 64 + oc + 1], 0.f);
                    *(float2*)(out + (((size_t)b * 256 + y) * 256 + x) * 128 +
                               oc) = make_float2(v0, v1);
                } else if constexpr (LAYER == 3) {
                    v0 = fmaxf(v0 + sb[oc], 0.f);
                    v1 = fmaxf(v1 + sb[oc + 1], 0.f);
                    *(float2*)(out + (((size_t)b * 256 + y) * 256 + x) * 64 +
                               oc) = make_float2(v0, v1);
                } else {
                    if (oc < 3)
                        out[(((size_t)b * 3 + oc) * 256 + y) * 256 + x] =
                            v0 + sb[oc];
                    if (oc + 1 < 3)
                        out[(((size_t)b * 3 + oc + 1) * 256 + y) * 256 + x] =
                            v1 + sb[oc + 1];
                }
            }
        }
    }
}

// ---------------------------------------------------------------------------
extern "C" void kernel_launch(void* const* d_in, const int* in_sizes, int n_in,
                              void* d_out, int out_size) {
    const float* x     = (const float*)d_in[0];
    const float* enc1  = (const float*)d_in[1];
    const float* enc2  = (const float*)d_in[2];
    const float* enc3  = (const float*)d_in[3];
    const float* style = (const float*)d_in[4];
    const float* w1    = (const float*)d_in[5];
    const float* fcw1  = (const float*)d_in[6];
    const float* fcb1  = (const float*)d_in[7];
    const float* w2    = (const float*)d_in[8];
    const float* fcw2  = (const float*)d_in[9];
    const float* fcb2  = (const float*)d_in[10];
    const float* fw1   = (const float*)d_in[11];
    const float* fb1   = (const float*)d_in[12];
    const float* fw2   = (const float*)d_in[13];
    const float* fb2   = (const float*)d_in[14];
    float* out = (float*)d_out;

    float *A1, *A2, *A3, *O3, *gw1, *gw2, *gw3, *gw4, *s1, *s2;
    cudaGetSymbolAddress((void**)&A1, g_A1);
    cudaGetSymbolAddress((void**)&A2, g_A2);
    cudaGetSymbolAddress((void**)&A3, g_A3);
    cudaGetSymbolAddress((void**)&O3, g_O3);
    cudaGetSymbolAddress((void**)&gw1, g_w1);
    cudaGetSymbolAddress((void**)&gw2, g_w2);
    cudaGetSymbolAddress((void**)&gw3, g_w3);
    cudaGetSymbolAddress((void**)&gw4, g_w4);
    cudaGetSymbolAddress((void**)&s1, g_s1);
    cudaGetSymbolAddress((void**)&s2, g_s2);

    cudaFuncSetAttribute(conv_mma<1>, cudaFuncAttributeMaxDynamicSharedMemorySize, SMEM_SZ);
    cudaFuncSetAttribute(conv_mma<2>, cudaFuncAttributeMaxDynamicSharedMemorySize, SMEM_SZ);
    cudaFuncSetAttribute(conv_mma<3>, cudaFuncAttributeMaxDynamicSharedMemorySize, SMEM_SZ);
    cudaFuncSetAttribute(conv_mma<4>, cudaFuncAttributeMaxDynamicSharedMemorySize, SMEM_SZ);

    // weight + style prep (tiny)
    wtrans<<<(9 * 512 * 128 + 255) / 256, 256>>>(w1, gw1, 128, 128, 512);
    wtrans<<<(9 * 256 * 64 + 255) / 256, 256>>>(w2, gw2, 64, 64, 256);
    wtrans<<<(9 * 128 * 64 + 255) / 256, 256>>>(fw1, gw3, 64, 64, 128);
    wtrans<<<(9 * 64 * 64 + 255) / 256, 256>>>(fw2, gw4, 3, 1 * 64, 64);
    style_mod<<<4, 256>>>(style, fcw1, fcb1, s1, 128);
    style_mod<<<2, 256>>>(style, fcw2, fcb2, s2, 64);

    // NHWC conversions (+up2)
    nchw2nhwc<true><<<dim3(8, 128, 8), 256>>>(x, A1, 256, 64, 128, 512, 0);
    nchw2nhwc<true><<<dim3(8, 128, 8), 256>>>(enc3, A1, 256, 64, 128, 512, 256);
    nchw2nhwc<true><<<dim3(8, 256, 8), 256>>>(enc2, A2, 128, 128, 256, 256, 128);
    nchw2nhwc<false><<<dim3(4, 256, 8), 256>>>(enc1, A3, 64, 256, 256, 128, 64);

    // convs (2-D tiles: L1 32x4 blocks of 128^2; L2-4 64x8 of 256^2)
    conv_mma<1><<<dim3(128, 16), 256, SMEM_SZ>>>(A1, gw1, s1, A2);
    conv_mma<2><<<dim3(512, 8), 256, SMEM_SZ>>>(A2, gw2, s2, A3);
    conv_mma<3><<<dim3(512, 8), 256, SMEM_SZ>>>(A3, gw3, fb1, O3);
    conv_mma<4><<<dim3(512, 8), 256, SMEM_SZ>>>(O3, gw4, fb2, out);
}

// round 12
// speedup vs baseline: 1.2109x; 1.2109x over previous
#include <cuda_runtime.h>
#include <cstdint>
#include <cstddef>

// ===========================================================================
// UNet decoder via warp-level tf32 mma.sync (tensor pipe).
// tcgen05 is NOT compilable through this bench (PTX target compute_103, no
// 'a' suffix) — warp MMA is the available tensor path.
// R11: revert conv to the proven R7 1x128 structure; force 3 CTAs/SM for
// phase overlap; fuse prep kernels + reorder so ncu (-s 5) captures conv1.
// ===========================================================================

__device__ float g_A1[8 * 128 * 128 * 512];  // up2(cat(x,enc3))
__device__ float g_A2[8 * 256 * 256 * 256];  // [conv1out_up | enc2_up]
__device__ float g_A3[8 * 256 * 256 * 128];  // [conv2out | enc1]
__device__ float g_O3[8 * 256 * 256 * 64];   // conv3out
__device__ float g_w1[9 * 512 * 128];        // gw[ky][kx][ic][oc], tf32-rounded
__device__ float g_w2[9 * 256 * 64];
__device__ float g_w3[9 * 128 * 64];
__device__ float g_w4[9 * 64 * 64];          // oc padded 3 -> 64
__device__ float g_s1[8 * 128];
__device__ float g_s2[8 * 64];

__device__ __forceinline__ uint32_t tf32r(float x) {
    uint32_t u;
    asm("cvt.rna.tf32.f32 %0, %1;" : "=r"(u) : "f"(x));
    return u;
}

__device__ __forceinline__ void mma8(float* c, const uint32_t* a, uint32_t b0,
                                     uint32_t b1) {
    asm volatile(
        "mma.sync.aligned.m16n8k8.row.col.f32.tf32.tf32.f32 "
        "{%0,%1,%2,%3}, {%4,%5,%6,%7}, {%8,%9}, {%0,%1,%2,%3};"
        : "+f"(c[0]), "+f"(c[1]), "+f"(c[2]), "+f"(c[3])
        : "r"(a[0]), "r"(a[1]), "r"(a[2]), "r"(a[3]), "r"(b0), "r"(b1));
}

// ---------------------------------------------------------------------------
// NCHW -> NHWC (+ optional nearest 2x upsample). Tile: 64 ch x 64 out-px.
// ---------------------------------------------------------------------------
template <bool UP>
__global__ __launch_bounds__(256) void nchw2nhwc(const float* __restrict__ src,
                                                 float* __restrict__ dst,
                                                 int Csrc, int Hsrc, int Wout,
                                                 int Crow, int coff) {
    constexpr int SXT = UP ? 32 : 64;
    __shared__ float sm[64][SXT + 1];
    const int xtiles = Wout >> 6;
    const int xt = blockIdx.x % xtiles;
    const int ct = blockIdx.x / xtiles;
    const int y = blockIdx.y, b = blockIdx.z;
    const int sy = UP ? (y >> 1) : y;
    const int t = threadIdx.x;

    const float* sp =
        src + ((size_t)(b * Csrc + ct * 64) * Hsrc + sy) * Hsrc + xt * SXT;
    for (int i = t; i < 64 * SXT / 4; i += 256) {
        int c = i / (SXT / 4), q = i % (SXT / 4);
        float4 v = *(const float4*)(sp + (size_t)c * Hsrc * Hsrc + q * 4);
        sm[c][q * 4 + 0] = v.x;
        sm[c][q * 4 + 1] = v.y;
        sm[c][q * 4 + 2] = v.z;
        sm[c][q * 4 + 3] = v.w;
    }
    __syncthreads();
    float* dp = dst + (((size_t)b * Wout + y) * Wout + xt * 64) * Crow + coff +
                ct * 64;
    for (int i = t; i < 1024; i += 256) {
        int x = i >> 4, cq = i & 15;
        int sx = UP ? (x >> 1) : x;
        float4 v = make_float4(sm[cq * 4 + 0][sx], sm[cq * 4 + 1][sx],
                               sm[cq * 4 + 2][sx], sm[cq * 4 + 3][sx]);
        *(float4*)(dp + (size_t)x * Crow + cq * 4) = v;
    }
}

// ---------------------------------------------------------------------------
// All weight transposes fused: w[oc][ic][ky][kx] ->
//   gw[((ky*3+kx)*IC+ic)*OCp + oc], tf32-rounded (zero-pad oc for L4).
// ---------------------------------------------------------------------------
__device__ __forceinline__ void wemit(const float* __restrict__ w,
                                      float* __restrict__ gw, int OCsrc,
                                      int OCp, int IC, int i) {
    int oc = i % OCp;
    int r = i / OCp;
    int ic = r % IC;
    r /= IC;
    int kx = r % 3, ky = r / 3;
    float v = (oc < OCsrc) ? w[((size_t)(oc * IC + ic) * 3 + ky) * 3 + kx] : 0.f;
    gw[i] = __uint_as_float(tf32r(v));
}

__global__ void wtransAll(const float* __restrict__ w1,
                          const float* __restrict__ w2,
                          const float* __restrict__ w3,
                          const float* __restrict__ w4, float* __restrict__ g1,
                          float* __restrict__ g2, float* __restrict__ g3,
                          float* __restrict__ g4) {
    constexpr int n1 = 9 * 512 * 128, n2 = 9 * 256 * 64, n3 = 9 * 128 * 64,
                  n4 = 9 * 64 * 64;
    int i = blockIdx.x * blockDim.x + threadIdx.x;
    if (i < n1) {
        wemit(w1, g1, 128, 128, 512, i);
    } else if (i < n1 + n2) {
        wemit(w2, g2, 64, 64, 256, i - n1);
    } else if (i < n1 + n2 + n3) {
        wemit(w3, g3, 64, 64, 128, i - n1 - n2);
    } else if (i < n1 + n2 + n3 + n4) {
        wemit(w4, g4, 3, 64, 64, i - n1 - n2 - n3);
    }
}

// ---------------------------------------------------------------------------
// Both style FCs fused: s[b][o] = style[b] . fcw[o] + fcb[o]
// ---------------------------------------------------------------------------
__global__ void styleAll(const float* __restrict__ style,
                         const float* __restrict__ fcw1,
                         const float* __restrict__ fcb1,
                         const float* __restrict__ fcw2,
                         const float* __restrict__ fcb2, float* __restrict__ s1,
                         float* __restrict__ s2) {
    int i = blockIdx.x * blockDim.x + threadIdx.x;
    const float* fcw;
    const float* fcb;
    float* s;
    int OC, j;
    if (i < 8 * 128) {
        fcw = fcw1; fcb = fcb1; s = s1; OC = 128; j = i;
    } else if (i < 8 * 128 + 8 * 64) {
        fcw = fcw2; fcb = fcb2; s = s2; OC = 64; j = i - 8 * 128;
    } else {
        return;
    }
    int b = j / OC, o = j - b * OC;
    const float* st = style + b * 256;
    const float* wp = fcw + o * 256;
    float a = fcb[o];
#pragma unroll 4
    for (int k = 0; k < 256; k++) a = fmaf(st[k], wp[k], a);
    s[j] = a;
}

// ---------------------------------------------------------------------------
// Implicit-GEMM conv3x3 (R7 structure). CTA = 128 px (row segment) x 64 oc,
// 8 warps as 4M x 2N, warp tile 32x32 via m16n8k8 tf32.
// LAYER: 1 512->128 @128^2 (scale,relu, 2x2-dup -> A2 ch0-127)
//        2 256->64  @256^2 (scale,relu -> A3 ch0-63)
//        3 128->64  @256^2 (+fb1,relu -> O3)
//        4  64->64p @256^2 (+fb2, oc<3 -> NCHW out)
// ---------------------------------------------------------------------------
template <int LAYER>
__global__ __launch_bounds__(256, 3) void conv_mma(
    const float* __restrict__ in, const float* __restrict__ gw,
    const float* __restrict__ sb, float* __restrict__ out) {
    constexpr int H = (LAYER == 1) ? 128 : 256;
    constexpr int W = H;
    constexpr int IC = (LAYER == 1) ? 512 : (LAYER == 2) ? 256
                       : (LAYER == 3) ? 128 : 64;
    constexpr int OCp = (LAYER == 1) ? 128 : 64;  // oc stride in gw
    constexpr int OCB = OCp / 64;
    constexpr int XB = W / 128;

    __shared__ uint32_t sA[130][36];      // [px(+2)][32 ch], stride 36
    __shared__ uint32_t sB[3][32][72];    // [kx][ic][64 oc], stride 72

    const int t = threadIdx.x, lane = t & 31, wid = t >> 5;
    const int g = lane >> 2, tig = lane & 3;
    const int wm = wid >> 1, wn = wid & 1;
    const int y = blockIdx.x / XB, x0 = (blockIdx.x % XB) * 128;
    const int b = blockIdx.y / OCB, ob = (blockIdx.y % OCB) * 64;

    float acc[2][4][4];
#pragma unroll
    for (int mt = 0; mt < 2; mt++)
#pragma unroll
        for (int nt = 0; nt < 4; nt++)
#pragma unroll
            for (int k = 0; k < 4; k++) acc[mt][nt][k] = 0.f;

    const float* inb = in + (size_t)b * H * W * IC;

    for (int ic0 = 0; ic0 < IC; ic0 += 32) {
        for (int ky = 0; ky < 3; ky++) {
            __syncthreads();
            // weight tile (pre-rounded): vectorized copy [kx][ic][oc]
            for (int i = t; i < 1536; i += 256) {
                const int oc4 = (i & 15) * 4;
                const int r = i >> 4;
                const int ic = r & 31, kx = r >> 5;
                *(uint4*)&sB[kx][ic][oc4] = *(const uint4*)(
                    gw + (size_t)((ky * 3 + kx) * IC + ic0 + ic) * OCp + ob +
                    oc4);
            }
            // activation slab: row y+ky-1, x0-1..x0+128, 32 channels
            const int gy = y + ky - 1;
            for (int i = t; i < 130 * 8; i += 256) {
                int px = i >> 3, q = i & 7;
                int gx = x0 - 1 + px;
                uint4 u = {0u, 0u, 0u, 0u};
                if (gy >= 0 && gy < H && gx >= 0 && gx < W) {
                    float4 f = *(const float4*)(inb + ((size_t)gy * W + gx) * IC +
                                                ic0 + q * 4);
                    u.x = tf32r(f.x); u.y = tf32r(f.y);
                    u.z = tf32r(f.z); u.w = tf32r(f.w);
                }
                *(uint4*)&sA[px][q * 4] = u;
            }
            __syncthreads();
#pragma unroll
            for (int kx = 0; kx < 3; kx++) {
#pragma unroll
                for (int ks = 0; ks < 4; ks++) {
                    const int kc = ks * 8;
                    uint32_t a[2][4];
#pragma unroll
                    for (int mt = 0; mt < 2; mt++) {
                        const int r0 = wm * 32 + mt * 16 + g + kx;
                        a[mt][0] = sA[r0][kc + tig];
                        a[mt][1] = sA[r0 + 8][kc + tig];
                        a[mt][2] = sA[r0][kc + tig + 4];
                        a[mt][3] = sA[r0 + 8][kc + tig + 4];
                    }
#pragma unroll
                    for (int nt = 0; nt < 4; nt++) {
                        const uint32_t b0 = sB[kx][kc + tig][wn * 32 + nt * 8 + g];
                        const uint32_t b1 =
                            sB[kx][kc + tig + 4][wn * 32 + nt * 8 + g];
                        mma8(acc[0][nt], a[0], b0, b1);
                        mma8(acc[1][nt], a[1], b0, b1);
                    }
                }
            }
        }
    }

    // ---------------- epilogue ----------------
#pragma unroll
    for (int mt = 0; mt < 2; mt++) {
#pragma unroll
        for (int nt = 0; nt < 4; nt++) {
            const int oc = ob + wn * 32 + nt * 8 + tig * 2;
#pragma unroll
            for (int h = 0; h < 2; h++) {  // c-rows: x and x+8
                const int x = x0 + wm * 32 + mt * 16 + g + h * 8;
                float v0 = acc[mt][nt][h * 2 + 0];
                float v1 = acc[mt][nt][h * 2 + 1];
                if constexpr (LAYER == 1) {
                    v0 = fmaxf(v0 * sb[b * 128 + oc], 0.f);
                    v1 = fmaxf(v1 * sb[b * 128 + oc + 1], 0.f);
                    float2 pv = make_float2(v0, v1);
#pragma unroll
                    for (int dy = 0; dy < 2; dy++)
#pragma unroll
                        for (int dx = 0; dx < 2; dx++)
                            *(float2*)(out +
                                       (((size_t)b * 256 + 2 * y + dy) * 256 +
                                        2 * x + dx) *
                                           256 +
                                       oc) = pv;
                } else if constexpr (LAYER == 2) {
                    v0 = fmaxf(v0 * sb[b * 64 + oc], 0.f);
                    v1 = fmaxf(v1 * sb[b * 64 + oc + 1], 0.f);
                    *(float2*)(out + (((size_t)b * 256 + y) * 256 + x) * 128 +
                               oc) = make_float2(v0, v1);
                } else if constexpr (LAYER == 3) {
                    v0 = fmaxf(v0 + sb[oc], 0.f);
                    v1 = fmaxf(v1 + sb[oc + 1], 0.f);
                    *(float2*)(out + (((size_t)b * 256 + y) * 256 + x) * 64 +
                               oc) = make_float2(v0, v1);
                } else {
                    if (oc < 3)
                        out[(((size_t)b * 3 + oc) * 256 + y) * 256 + x] =
                            v0 + sb[oc];
                    if (oc + 1 < 3)
                        out[(((size_t)b * 3 + oc + 1) * 256 + y) * 256 + x] =
                            v1 + sb[oc + 1];
                }
            }
        }
    }
}

// ---------------------------------------------------------------------------
extern "C" void kernel_launch(void* const* d_in, const int* in_sizes, int n_in,
                              void* d_out, int out_size) {
    const float* x     = (const float*)d_in[0];
    const float* enc1  = (const float*)d_in[1];
    const float* enc2  = (const float*)d_in[2];
    const float* enc3  = (const float*)d_in[3];
    const float* style = (const float*)d_in[4];
    const float* w1    = (const float*)d_in[5];
    const float* fcw1  = (const float*)d_in[6];
    const float* fcb1  = (const float*)d_in[7];
    const float* w2    = (const float*)d_in[8];
    const float* fcw2  = (const float*)d_in[9];
    const float* fcb2  = (const float*)d_in[10];
    const float* fw1   = (const float*)d_in[11];
    const float* fb1   = (const float*)d_in[12];
    const float* fw2   = (const float*)d_in[13];
    const float* fb2   = (const float*)d_in[14];
    float* out = (float*)d_out;

    float *A1, *A2, *A3, *O3, *gw1, *gw2, *gw3, *gw4, *s1, *s2;
    cudaGetSymbolAddress((void**)&A1, g_A1);
    cudaGetSymbolAddress((void**)&A2, g_A2);
    cudaGetSymbolAddress((void**)&A3, g_A3);
    cudaGetSymbolAddress((void**)&O3, g_O3);
    cudaGetSymbolAddress((void**)&gw1, g_w1);
    cudaGetSymbolAddress((void**)&gw2, g_w2);
    cudaGetSymbolAddress((void**)&gw3, g_w3);
    cudaGetSymbolAddress((void**)&gw4, g_w4);
    cudaGetSymbolAddress((void**)&s1, g_s1);
    cudaGetSymbolAddress((void**)&s2, g_s2);

    constexpr int NW =
        9 * 512 * 128 + 9 * 256 * 64 + 9 * 128 * 64 + 9 * 64 * 64;

    // Launch order chosen so index 5 (ncu -s 5 -c 1) is conv_mma<1>.
    /*0*/ wtransAll<<<(NW + 255) / 256, 256>>>(w1, w2, fw1, fw2, gw1, gw2, gw3,
                                               gw4);
    /*1*/ styleAll<<<6, 256>>>(style, fcw1, fcb1, fcw2, fcb2, s1, s2);
    /*2*/ nchw2nhwc<true><<<dim3(8, 128, 8), 256>>>(x, A1, 256, 64, 128, 512, 0);
    /*3*/ nchw2nhwc<true><<<dim3(8, 128, 8), 256>>>(enc3, A1, 256, 64, 128, 512,
                                                    256);
    /*4*/ nchw2nhwc<true><<<dim3(8, 256, 8), 256>>>(enc2, A2, 128, 128, 256, 256,
                                                    128);
    /*5*/ conv_mma<1><<<dim3(128, 16), 256>>>(A1, gw1, s1, A2);
    /*6*/ nchw2nhwc<false><<<dim3(4, 256, 8), 256>>>(enc1, A3, 64, 256, 256, 128,
                                                     64);
    /*7*/ conv_mma<2><<<dim3(512, 8), 256>>>(A2, gw2, s2, A3);
    /*8*/ conv_mma<3><<<dim3(512, 8), 256>>>(A3, gw3, fb1, O3);
    /*9*/ conv_mma<4><<<dim3(512, 8), 256>>>(O3, gw4, fb2, out);
}

// round 14
// speedup vs baseline: 2.1685x; 1.7908x over previous
#include <cuda_runtime.h>
#include <cuda_fp16.h>
#include <cstdint>
#include <cstddef>

// ===========================================================================
// UNet decoder via warp-level fp16 mma.sync (m16n8k16, fp32 accumulate).
// fp16 significand (11 bits) == tf32 significand, so precision matches the
// tf32 version while doubling MACs/instruction and halving operand traffic.
// Activations stored as half NHWC; weights pre-packed to [ky][kx][oc][ic/2]
// half2. tcgen05 remains uncompilable at this bench's compute_103 target.
// ===========================================================================

__device__ __half g_A1[8 * 128 * 128 * 512];  // up2(cat(x,enc3))
__device__ __half g_A2[8 * 256 * 256 * 256];  // [conv1out_up | enc2_up]
__device__ __half g_A3[8 * 256 * 256 * 128];  // [conv2out | enc1]
__device__ __half g_O3[8 * 256 * 256 * 64];   // conv3out
__device__ uint32_t g_w1[9 * 128 * 256];      // [ky][kx][oc][ic2] half2
__device__ uint32_t g_w2[9 * 64 * 128];
__device__ uint32_t g_w3[9 * 64 * 64];
__device__ uint32_t g_w4[9 * 64 * 32];        // oc padded 3 -> 64
__device__ float g_s1[8 * 128];
__device__ float g_s2[8 * 64];

__device__ __forceinline__ void mma16(float* c, const uint32_t* a, uint32_t b0,
                                      uint32_t b1) {
    asm volatile(
        "mma.sync.aligned.m16n8k16.row.col.f32.f16.f16.f32 "
        "{%0,%1,%2,%3}, {%4,%5,%6,%7}, {%8,%9}, {%0,%1,%2,%3};"
        : "+f"(c[0]), "+f"(c[1]), "+f"(c[2]), "+f"(c[3])
        : "r"(a[0]), "r"(a[1]), "r"(a[2]), "r"(a[3]), "r"(b0), "r"(b1));
}

// ---------------------------------------------------------------------------
// NCHW fp32 -> NHWC half (+ optional nearest 2x upsample). 64ch x 64px tile.
// ---------------------------------------------------------------------------
template <bool UP>
__global__ __launch_bounds__(256) void nchw2nhwc(const float* __restrict__ src,
                                                 __half* __restrict__ dst,
                                                 int Csrc, int Hsrc, int Wout,
                                                 int Crow, int coff) {
    constexpr int SXT = UP ? 32 : 64;
    __shared__ float sm[64][SXT + 1];
    const int xtiles = Wout >> 6;
    const int xt = blockIdx.x % xtiles;
    const int ct = blockIdx.x / xtiles;
    const int y = blockIdx.y, b = blockIdx.z;
    const int sy = UP ? (y >> 1) : y;
    const int t = threadIdx.x;

    const float* sp =
        src + ((size_t)(b * Csrc + ct * 64) * Hsrc + sy) * Hsrc + xt * SXT;
    for (int i = t; i < 64 * SXT / 4; i += 256) {
        int c = i / (SXT / 4), q = i % (SXT / 4);
        float4 v = *(const float4*)(sp + (size_t)c * Hsrc * Hsrc + q * 4);
        sm[c][q * 4 + 0] = v.x;
        sm[c][q * 4 + 1] = v.y;
        sm[c][q * 4 + 2] = v.z;
        sm[c][q * 4 + 3] = v.w;
    }
    __syncthreads();
    __half* dp = dst + (((size_t)b * Wout + y) * Wout + xt * 64) * Crow + coff +
                 ct * 64;
    for (int i = t; i < 1024; i += 256) {
        int x = i >> 4, cq = i & 15;
        int sx = UP ? (x >> 1) : x;
        __half2 h0 = __floats2half2_rn(sm[cq * 4 + 0][sx], sm[cq * 4 + 1][sx]);
        __half2 h1 = __floats2half2_rn(sm[cq * 4 + 2][sx], sm[cq * 4 + 3][sx]);
        uint2 u;
        u.x = *(uint32_t*)&h0;
        u.y = *(uint32_t*)&h1;
        *(uint2*)(dp + (size_t)x * Crow + cq * 4) = u;
    }
}

// ---------------------------------------------------------------------------
// Weight pack (all 4 layers fused): w[oc][ic][ky][kx] fp32 ->
//   gw[((ky*3+kx)*OCp + oc)*IC2 + ic2] = half2(w[.. 2*ic2 ..], w[.. 2*ic2+1 ..])
// ---------------------------------------------------------------------------
__device__ __forceinline__ void wemit(const float* __restrict__ w,
                                      uint32_t* __restrict__ gw, int OCsrc,
                                      int OCp, int IC, int i) {
    const int IC2 = IC >> 1;
    int ic2 = i % IC2;
    int r = i / IC2;
    int oc = r % OCp;
    r /= OCp;
    int kx = r % 3, ky = r / 3;
    float v0 = 0.f, v1 = 0.f;
    if (oc < OCsrc) {
        v0 = w[((size_t)(oc * IC + 2 * ic2) * 3 + ky) * 3 + kx];
        v1 = w[((size_t)(oc * IC + 2 * ic2 + 1) * 3 + ky) * 3 + kx];
    }
    __half2 h = __floats2half2_rn(v0, v1);
    gw[i] = *(uint32_t*)&h;
}

__global__ void wtransAll(const float* __restrict__ w1,
                          const float* __restrict__ w2,
                          const float* __restrict__ w3,
                          const float* __restrict__ w4,
                          uint32_t* __restrict__ g1, uint32_t* __restrict__ g2,
                          uint32_t* __restrict__ g3,
                          uint32_t* __restrict__ g4) {
    constexpr int n1 = 9 * 128 * 256, n2 = 9 * 64 * 128, n3 = 9 * 64 * 64,
                  n4 = 9 * 64 * 32;
    int i = blockIdx.x * blockDim.x + threadIdx.x;
    if (i < n1) {
        wemit(w1, g1, 128, 128, 512, i);
    } else if (i < n1 + n2) {
        wemit(w2, g2, 64, 64, 256, i - n1);
    } else if (i < n1 + n2 + n3) {
        wemit(w3, g3, 64, 64, 128, i - n1 - n2);
    } else if (i < n1 + n2 + n3 + n4) {
        wemit(w4, g4, 3, 64, 64, i - n1 - n2 - n3);
    }
}

// ---------------------------------------------------------------------------
// Both style FCs fused.
// ---------------------------------------------------------------------------
__global__ void styleAll(const float* __restrict__ style,
                         const float* __restrict__ fcw1,
                         const float* __restrict__ fcb1,
                         const float* __restrict__ fcw2,
                         const float* __restrict__ fcb2, float* __restrict__ s1,
                         float* __restrict__ s2) {
    int i = blockIdx.x * blockDim.x + threadIdx.x;
    const float* fcw;
    const float* fcb;
    float* s;
    int OC, j;
    if (i < 8 * 128) {
        fcw = fcw1; fcb = fcb1; s = s1; OC = 128; j = i;
    } else if (i < 8 * 128 + 8 * 64) {
        fcw = fcw2; fcb = fcb2; s = s2; OC = 64; j = i - 8 * 128;
    } else {
        return;
    }
    int b = j / OC, o = j - b * OC;
    const float* st = style + b * 256;
    const float* wp = fcw + o * 256;
    float a = fcb[o];
#pragma unroll 4
    for (int k = 0; k < 256; k++) a = fmaf(st[k], wp[k], a);
    s[j] = a;
}

// ---------------------------------------------------------------------------
// Implicit-GEMM conv3x3, fp16 m16n8k16. CTA = 128 px x 64 oc, 8 warps 4Mx2N.
// sA[130][20]: half2 words, [px][ic2] (16 used, stride 20 => conflict-free)
// sB[3][64][20]: [kx][oc][ic2]  (B fragment = single LDS.32)
// LAYER: 1 512->128 @128^2 (scale,relu, 2x2-dup -> A2 ch0-127)
//        2 256->64  @256^2 (scale,relu -> A3 ch0-63)
//        3 128->64  @256^2 (+fb1,relu -> O3)
//        4  64->64p @256^2 (+fb2, oc<3 -> NCHW fp32 out)
// ---------------------------------------------------------------------------
template <int LAYER>
__global__ __launch_bounds__(256, 3) void conv_mma(
    const __half* __restrict__ in, const uint32_t* __restrict__ gw,
    const float* __restrict__ sb, void* __restrict__ outv) {
    constexpr int H = (LAYER == 1) ? 128 : 256;
    constexpr int W = H;
    constexpr int IC = (LAYER == 1) ? 512 : (LAYER == 2) ? 256
                       : (LAYER == 3) ? 128 : 64;
    constexpr int IC2 = IC >> 1;
    constexpr int OCp = (LAYER == 1) ? 128 : 64;
    constexpr int OCB = OCp / 64;
    constexpr int XB = W / 128;

    __shared__ uint32_t sA[130][20];
    __shared__ uint32_t sB[3][64][20];

    const int t = threadIdx.x, lane = t & 31, wid = t >> 5;
    const int g = lane >> 2, tig = lane & 3;
    const int wm = wid >> 1, wn = wid & 1;
    const int y = blockIdx.x / XB, x0 = (blockIdx.x % XB) * 128;
    const int b = blockIdx.y / OCB, ob = (blockIdx.y % OCB) * 64;

    float acc[2][4][4];
#pragma unroll
    for (int mt = 0; mt < 2; mt++)
#pragma unroll
        for (int nt = 0; nt < 4; nt++)
#pragma unroll
            for (int k = 0; k < 4; k++) acc[mt][nt][k] = 0.f;

    const __half* inb = in + (size_t)b * H * W * IC;

    for (int ic0 = 0; ic0 < IC; ic0 += 32) {
        for (int ky = 0; ky < 3; ky++) {
            __syncthreads();
            // ---- B tile: [kx][oc][ic2], straight uint4 copy (768 items) ----
            for (int i = t; i < 768; i += 256) {
                const int q4 = i & 3;
                const int oc = (i >> 2) & 63;
                const int kx = i >> 8;
                *(uint4*)&sB[kx][oc][q4 * 4] = *(const uint4*)(
                    gw + (size_t)((ky * 3 + kx) * OCp + ob + oc) * IC2 +
                    (ic0 >> 1) + q4 * 4);
            }
            // ---- A slab: row y+ky-1, 130 px x 32 ch (16 half2 words) ----
            const int gy = y + ky - 1;
            for (int i = t; i < 520; i += 256) {
                const int px = i >> 2, q = i & 3;
                const int gx = x0 - 1 + px;
                uint4 u = {0u, 0u, 0u, 0u};
                if (gy >= 0 && gy < H && gx >= 0 && gx < W)
                    u = *(const uint4*)(inb + ((size_t)gy * W + gx) * IC + ic0 +
                                        q * 8);
                *(uint4*)&sA[px][q * 4] = u;
            }
            __syncthreads();
#pragma unroll
            for (int kx = 0; kx < 3; kx++) {
#pragma unroll
                for (int ks = 0; ks < 2; ks++) {
                    const int kb = ks * 8;
                    uint32_t a[2][4];
#pragma unroll
                    for (int mt = 0; mt < 2; mt++) {
                        const int r0 = wm * 32 + mt * 16 + g + kx;
                        a[mt][0] = sA[r0][kb + tig];
                        a[mt][1] = sA[r0 + 8][kb + tig];
                        a[mt][2] = sA[r0][kb + tig + 4];
                        a[mt][3] = sA[r0 + 8][kb + tig + 4];
                    }
#pragma unroll
                    for (int nt = 0; nt < 4; nt++) {
                        const int oc = wn * 32 + nt * 8 + g;
                        const uint32_t b0 = sB[kx][oc][kb + tig];
                        const uint32_t b1 = sB[kx][oc][kb + tig + 4];
                        mma16(acc[0][nt], a[0], b0, b1);
                        mma16(acc[1][nt], a[1], b0, b1);
                    }
                }
            }
        }
    }

    // ---------------- epilogue ----------------
#pragma unroll
    for (int mt = 0; mt < 2; mt++) {
#pragma unroll
        for (int nt = 0; nt < 4; nt++) {
            const int oc = ob + wn * 32 + nt * 8 + tig * 2;
#pragma unroll
            for (int h = 0; h < 2; h++) {  // c-rows: x and x+8
                const int x = x0 + wm * 32 + mt * 16 + g + h * 8;
                float v0 = acc[mt][nt][h * 2 + 0];
                float v1 = acc[mt][nt][h * 2 + 1];
                if constexpr (LAYER == 1) {
                    v0 = fmaxf(v0 * sb[b * 128 + oc], 0.f);
                    v1 = fmaxf(v1 * sb[b * 128 + oc + 1], 0.f);
                    __half2 hv = __floats2half2_rn(v0, v1);
                    uint32_t u = *(uint32_t*)&hv;
                    __half* out = (__half*)outv;
#pragma unroll
                    for (int dy = 0; dy < 2; dy++)
#pragma unroll
                        for (int dx = 0; dx < 2; dx++)
                            *(uint32_t*)(out +
                                         (((size_t)b * 256 + 2 * y + dy) * 256 +
                                          2 * x + dx) *
                                             256 +
                                         oc) = u;
                } else if constexpr (LAYER == 2) {
                    v0 = fmaxf(v0 * sb[b * 64 + oc], 0.f);
                    v1 = fmaxf(v1 * sb[b * 64 + oc + 1], 0.f);
                    __half2 hv = __floats2half2_rn(v0, v1);
                    *(uint32_t*)((__half*)outv +
                                 (((size_t)b * 256 + y) * 256 + x) * 128 + oc) =
                        *(uint32_t*)&hv;
                } else if constexpr (LAYER == 3) {
                    v0 = fmaxf(v0 + sb[oc], 0.f);
                    v1 = fmaxf(v1 + sb[oc + 1], 0.f);
                    __half2 hv = __floats2half2_rn(v0, v1);
                    *(uint32_t*)((__half*)outv +
                                 (((size_t)b * 256 + y) * 256 + x) * 64 + oc) =
                        *(uint32_t*)&hv;
                } else {
                    float* out = (float*)outv;
                    if (oc < 3)
                        out[(((size_t)b * 3 + oc) * 256 + y) * 256 + x] =
                            v0 + sb[oc];
                    if (oc + 1 < 3)
                        out[(((size_t)b * 3 + oc + 1) * 256 + y) * 256 + x] =
                            v1 + sb[oc + 1];
                }
            }
        }
    }
}

// ---------------------------------------------------------------------------
extern "C" void kernel_launch(void* const* d_in, const int* in_sizes, int n_in,
                              void* d_out, int out_size) {
    const float* x     = (const float*)d_in[0];
    const float* enc1  = (const float*)d_in[1];
    const float* enc2  = (const float*)d_in[2];
    const float* enc3  = (const float*)d_in[3];
    const float* style = (const float*)d_in[4];
    const float* w1    = (const float*)d_in[5];
    const float* fcw1  = (const float*)d_in[6];
    const float* fcb1  = (const float*)d_in[7];
    const float* w2    = (const float*)d_in[8];
    const float* fcw2  = (const float*)d_in[9];
    const float* fcb2  = (const float*)d_in[10];
    const float* fw1   = (const float*)d_in[11];
    const float* fb1   = (const float*)d_in[12];
    const float* fw2   = (const float*)d_in[13];
    const float* fb2   = (const float*)d_in[14];
    float* out = (float*)d_out;

    __half *A1, *A2, *A3, *O3;
    uint32_t *gw1, *gw2, *gw3, *gw4;
    float *s1, *s2;
    cudaGetSymbolAddress((void**)&A1, g_A1);
    cudaGetSymbolAddress((void**)&A2, g_A2);
    cudaGetSymbolAddress((void**)&A3, g_A3);
    cudaGetSymbolAddress((void**)&O3, g_O3);
    cudaGetSymbolAddress((void**)&gw1, g_w1);
    cudaGetSymbolAddress((void**)&gw2, g_w2);
    cudaGetSymbolAddress((void**)&gw3, g_w3);
    cudaGetSymbolAddress((void**)&gw4, g_w4);
    cudaGetSymbolAddress((void**)&s1, g_s1);
    cudaGetSymbolAddress((void**)&s2, g_s2);

    constexpr int NW = 9 * 128 * 256 + 9 * 64 * 128 + 9 * 64 * 64 + 9 * 64 * 32;

    // Launch order keeps conv_mma<1> at index 5 for ncu -s 5 -c 1.
    /*0*/ wtransAll<<<(NW + 255) / 256, 256>>>(w1, w2, fw1, fw2, gw1, gw2, gw3,
                                               gw4);
    /*1*/ styleAll<<<6, 256>>>(style, fcw1, fcb1, fcw2, fcb2, s1, s2);
    /*2*/ nchw2nhwc<true><<<dim3(8, 128, 8), 256>>>(x, A1, 256, 64, 128, 512, 0);
    /*3*/ nchw2nhwc<true><<<dim3(8, 128, 8), 256>>>(enc3, A1, 256, 64, 128, 512,
                                                    256);
    /*4*/ nchw2nhwc<true><<<dim3(8, 256, 8), 256>>>(enc2, A2, 128, 128, 256, 256,
                                                    128);
    /*5*/ conv_mma<1><<<dim3(128, 16), 256>>>(A1, gw1, s1, A2);
    /*6*/ nchw2nhwc<false><<<dim3(4, 256, 8), 256>>>(enc1, A3, 64, 256, 256, 128,
                                                     64);
    /*7*/ conv_mma<2><<<dim3(512, 8), 256>>>(A2, gw2, s2, A3);
    /*8*/ conv_mma<3><<<dim3(512, 8), 256>>>(A3, gw3, fb1, O3);
    /*9*/ conv_mma<4><<<dim3(512, 8), 256>>>(O3, gw4, fb2, out);
}

// round 16
// speedup vs baseline: 2.5907x; 1.1947x over previous
#include <cuda_runtime.h>
#include <cuda_fp16.h>
#include <cstdint>
#include <cstddef>

// ===========================================================================
// UNet decoder via warp-level fp16 mma.sync (m16n8k16, fp32 accumulate).
// R15: cp.async double-buffered operand pipeline in the conv mainloop
// (1 sync/phase, loads overlap HMMA); dedicated narrow-N kernel for the
// final 64->3 conv. Activations half NHWC; weights pre-packed half2.
// ===========================================================================

__device__ __half g_A1[8 * 128 * 128 * 512];  // up2(cat(x,enc3))
__device__ __half g_A2[8 * 256 * 256 * 256];  // [conv1out_up | enc2_up]
__device__ __half g_A3[8 * 256 * 256 * 128];  // [conv2out | enc1]
__device__ __half g_O3[8 * 256 * 256 * 64];   // conv3out
__device__ uint32_t g_w1[9 * 128 * 256];      // [ky][kx][oc][ic2] half2
__device__ uint32_t g_w2[9 * 64 * 128];
__device__ uint32_t g_w3[9 * 64 * 64];
__device__ uint32_t g_w4[9 * 8 * 32];         // L4: oc padded 3 -> 8
__device__ float g_s1[8 * 128];
__device__ float g_s2[8 * 64];

__device__ __forceinline__ void mma16(float* c, const uint32_t* a, uint32_t b0,
                                      uint32_t b1) {
    asm volatile(
        "mma.sync.aligned.m16n8k16.row.col.f32.f16.f16.f32 "
        "{%0,%1,%2,%3}, {%4,%5,%6,%7}, {%8,%9}, {%0,%1,%2,%3};"
        : "+f"(c[0]), "+f"(c[1]), "+f"(c[2]), "+f"(c[3])
        : "r"(a[0]), "r"(a[1]), "r"(a[2]), "r"(a[3]), "r"(b0), "r"(b1));
}

// cp.async 16B with zero-fill when pred is false (src-size = 0).
__device__ __forceinline__ void cp16(uint32_t dst, const void* src, bool pred) {
    asm volatile("cp.async.ca.shared.global [%0], [%1], 16, %2;"
                 :: "r"(dst), "l"(src), "r"(pred ? 16 : 0));
}

// ---------------------------------------------------------------------------
// NCHW fp32 -> NHWC half (+ optional nearest 2x upsample). 64ch x 64px tile.
// ---------------------------------------------------------------------------
template <bool UP>
__global__ __launch_bounds__(256) void nchw2nhwc(const float* __restrict__ src,
                                                 __half* __restrict__ dst,
                                                 int Csrc, int Hsrc, int Wout,
                                                 int Crow, int coff) {
    constexpr int SXT = UP ? 32 : 64;
    __shared__ float sm[64][SXT + 1];
    const int xtiles = Wout >> 6;
    const int xt = blockIdx.x % xtiles;
    const int ct = blockIdx.x / xtiles;
    const int y = blockIdx.y, b = blockIdx.z;
    const int sy = UP ? (y >> 1) : y;
    const int t = threadIdx.x;

    const float* sp =
        src + ((size_t)(b * Csrc + ct * 64) * Hsrc + sy) * Hsrc + xt * SXT;
    for (int i = t; i < 64 * SXT / 4; i += 256) {
        int c = i / (SXT / 4), q = i % (SXT / 4);
        float4 v = *(const float4*)(sp + (size_t)c * Hsrc * Hsrc + q * 4);
        sm[c][q * 4 + 0] = v.x;
        sm[c][q * 4 + 1] = v.y;
        sm[c][q * 4 + 2] = v.z;
        sm[c][q * 4 + 3] = v.w;
    }
    __syncthreads();
    __half* dp = dst + (((size_t)b * Wout + y) * Wout + xt * 64) * Crow + coff +
                 ct * 64;
    for (int i = t; i < 1024; i += 256) {
        int x = i >> 4, cq = i & 15;
        int sx = UP ? (x >> 1) : x;
        __half2 h0 = __floats2half2_rn(sm[cq * 4 + 0][sx], sm[cq * 4 + 1][sx]);
        __half2 h1 = __floats2half2_rn(sm[cq * 4 + 2][sx], sm[cq * 4 + 3][sx]);
        uint2 u;
        u.x = *(uint32_t*)&h0;
        u.y = *(uint32_t*)&h1;
        *(uint2*)(dp + (size_t)x * Crow + cq * 4) = u;
    }
}

// ---------------------------------------------------------------------------
// Weight pack (all 4 layers fused): w[oc][ic][ky][kx] fp32 ->
//   gw[((ky*3+kx)*OCp + oc)*IC2 + ic2] half2, zero-padded oc.
// ---------------------------------------------------------------------------
__device__ __forceinline__ void wemit(const float* __restrict__ w,
                                      uint32_t* __restrict__ gw, int OCsrc,
                                      int OCp, int IC, int i) {
    const int IC2 = IC >> 1;
    int ic2 = i % IC2;
    int r = i / IC2;
    int oc = r % OCp;
    r /= OCp;
    int kx = r % 3, ky = r / 3;
    float v0 = 0.f, v1 = 0.f;
    if (oc < OCsrc) {
        v0 = w[((size_t)(oc * IC + 2 * ic2) * 3 + ky) * 3 + kx];
        v1 = w[((size_t)(oc * IC + 2 * ic2 + 1) * 3 + ky) * 3 + kx];
    }
    __half2 h = __floats2half2_rn(v0, v1);
    gw[i] = *(uint32_t*)&h;
}

__global__ void wtransAll(const float* __restrict__ w1,
                          const float* __restrict__ w2,
                          const float* __restrict__ w3,
                          const float* __restrict__ w4,
                          uint32_t* __restrict__ g1, uint32_t* __restrict__ g2,
                          uint32_t* __restrict__ g3,
                          uint32_t* __restrict__ g4) {
    constexpr int n1 = 9 * 128 * 256, n2 = 9 * 64 * 128, n3 = 9 * 64 * 64,
                  n4 = 9 * 8 * 32;
    int i = blockIdx.x * blockDim.x + threadIdx.x;
    if (i < n1) {
        wemit(w1, g1, 128, 128, 512, i);
    } else if (i < n1 + n2) {
        wemit(w2, g2, 64, 64, 256, i - n1);
    } else if (i < n1 + n2 + n3) {
        wemit(w3, g3, 64, 64, 128, i - n1 - n2);
    } else if (i < n1 + n2 + n3 + n4) {
        wemit(w4, g4, 3, 8, 64, i - n1 - n2 - n3);
    }
}

// ---------------------------------------------------------------------------
// Both style FCs fused.
// ---------------------------------------------------------------------------
__global__ void styleAll(const float* __restrict__ style,
                         const float* __restrict__ fcw1,
                         const float* __restrict__ fcb1,
                         const float* __restrict__ fcw2,
                         const float* __restrict__ fcb2, float* __restrict__ s1,
                         float* __restrict__ s2) {
    int i = blockIdx.x * blockDim.x + threadIdx.x;
    const float* fcw;
    const float* fcb;
    float* s;
    int OC, j;
    if (i < 8 * 128) {
        fcw = fcw1; fcb = fcb1; s = s1; OC = 128; j = i;
    } else if (i < 8 * 128 + 8 * 64) {
        fcw = fcw2; fcb = fcb2; s = s2; OC = 64; j = i - 8 * 128;
    } else {
        return;
    }
    int b = j / OC, o = j - b * OC;
    const float* st = style + b * 256;
    const float* wp = fcw + o * 256;
    float a = fcb[o];
#pragma unroll 4
    for (int k = 0; k < 256; k++) a = fmaf(st[k], wp[k], a);
    s[j] = a;
}

// ---------------------------------------------------------------------------
// Implicit-GEMM conv3x3, fp16 m16n8k16, cp.async double-buffered.
// CTA = 128 px x 64 oc, 8 warps 4Mx2N, warp tile 32x32.
// Dynamic SMEM (uint32 words): A = 2 x 130x20 (5200), B = 2 x 3x64x20 (7680).
// LAYER: 1 512->128 @128^2 (scale,relu, 2x2-dup -> A2 ch0-127)
//        2 256->64  @256^2 (scale,relu -> A3 ch0-63)
//        3 128->64  @256^2 (+fb1,relu -> O3)
// ---------------------------------------------------------------------------
static constexpr int AW = 130 * 20;            // words per A buffer
static constexpr int BW = 3 * 64 * 20;         // words per B buffer
static constexpr int DYN_W = 2 * AW + 2 * BW;  // 12880 words = 51520 B
static constexpr int DYN_B = DYN_W * 4;

template <int LAYER>
__global__ __launch_bounds__(256, 3) void conv_mma(
    const __half* __restrict__ in, const uint32_t* __restrict__ gw,
    const float* __restrict__ sb, void* __restrict__ outv) {
    constexpr int H = (LAYER == 1) ? 128 : 256;
    constexpr int W = H;
    constexpr int IC = (LAYER == 1) ? 512 : (LAYER == 2) ? 256 : 128;
    constexpr int IC2 = IC >> 1;
    constexpr int OCp = (LAYER == 1) ? 128 : 64;
    constexpr int OCB = OCp / 64;
    constexpr int XB = W / 128;
    constexpr int P = (IC / 32) * 3;  // passes

    extern __shared__ uint32_t dyn[];
    const uint32_t smem32 = (uint32_t)__cvta_generic_to_shared(dyn);

    const int t = threadIdx.x, lane = t & 31, wid = t >> 5;
    const int g = lane >> 2, tig = lane & 3;
    const int wm = wid >> 1, wn = wid & 1;
    const int y = blockIdx.x / XB, x0 = (blockIdx.x % XB) * 128;
    const int b = blockIdx.y / OCB, ob = (blockIdx.y % OCB) * 64;

    const __half* inb = in + (size_t)b * H * W * IC;

    auto prefetch = [&](int p, int buf) {
        const int ic0 = (p / 3) * 32;
        const int ky = p - (p / 3) * 3;
        const int gy = y + ky - 1;
        const uint32_t bbase = smem32 + (2 * AW + buf * BW) * 4;
        for (int i = t; i < 768; i += 256) {
            const int q4 = i & 3, oc = (i >> 2) & 63, kx = i >> 8;
            cp16(bbase + (kx * 1280 + oc * 20 + q4 * 4) * 4,
                 gw + (size_t)((ky * 3 + kx) * OCp + ob + oc) * IC2 +
                     (ic0 >> 1) + q4 * 4,
                 true);
        }
        const uint32_t abase = smem32 + buf * AW * 4;
        const bool yok = (gy >= 0 && gy < H);
        for (int i = t; i < 520; i += 256) {
            const int px = i >> 2, q = i & 3;
            const int gx = x0 - 1 + px;
            cp16(abase + (px * 20 + q * 4) * 4,
                 inb + ((size_t)gy * W + gx) * IC + ic0 + q * 8,
                 yok && gx >= 0 && gx < W);
        }
        asm volatile("cp.async.commit_group;" ::: "memory");
    };

    float acc[2][4][4];
#pragma unroll
    for (int mt = 0; mt < 2; mt++)
#pragma unroll
        for (int nt = 0; nt < 4; nt++)
#pragma unroll
            for (int k = 0; k < 4; k++) acc[mt][nt][k] = 0.f;

    prefetch(0, 0);
    for (int p = 0; p < P; p++) {
        asm volatile("cp.async.wait_group 0;" ::: "memory");
        __syncthreads();
        if (p + 1 < P) prefetch(p + 1, (p + 1) & 1);
        const uint32_t(*sA)[20] = (const uint32_t(*)[20])(dyn + (p & 1) * AW);
        const uint32_t(*sB)[64][20] =
            (const uint32_t(*)[64][20])(dyn + 2 * AW + (p & 1) * BW);
#pragma unroll
        for (int kx = 0; kx < 3; kx++) {
#pragma unroll
            for (int ks = 0; ks < 2; ks++) {
                const int kb = ks * 8;
                uint32_t a[2][4];
#pragma unroll
                for (int mt = 0; mt < 2; mt++) {
                    const int r0 = wm * 32 + mt * 16 + g + kx;
                    a[mt][0] = sA[r0][kb + tig];
                    a[mt][1] = sA[r0 + 8][kb + tig];
                    a[mt][2] = sA[r0][kb + tig + 4];
                    a[mt][3] = sA[r0 + 8][kb + tig + 4];
                }
#pragma unroll
                for (int nt = 0; nt < 4; nt++) {
                    const int oc = wn * 32 + nt * 8 + g;
                    const uint32_t b0 = sB[kx][oc][kb + tig];
                    const uint32_t b1 = sB[kx][oc][kb + tig + 4];
                    mma16(acc[0][nt], a[0], b0, b1);
                    mma16(acc[1][nt], a[1], b0, b1);
                }
            }
        }
        __syncthreads();
    }

    // ---------------- epilogue ----------------
#pragma unroll
    for (int mt = 0; mt < 2; mt++) {
#pragma unroll
        for (int nt = 0; nt < 4; nt++) {
            const int oc = ob + wn * 32 + nt * 8 + tig * 2;
#pragma unroll
            for (int h = 0; h < 2; h++) {  // c-rows: x and x+8
                const int x = x0 + wm * 32 + mt * 16 + g + h * 8;
                float v0 = acc[mt][nt][h * 2 + 0];
                float v1 = acc[mt][nt][h * 2 + 1];
                if constexpr (LAYER == 1) {
                    v0 = fmaxf(v0 * sb[b * 128 + oc], 0.f);
                    v1 = fmaxf(v1 * sb[b * 128 + oc + 1], 0.f);
                    __half2 hv = __floats2half2_rn(v0, v1);
                    uint32_t u = *(uint32_t*)&hv;
                    __half* out = (__half*)outv;
#pragma unroll
                    for (int dy = 0; dy < 2; dy++)
#pragma unroll
                        for (int dx = 0; dx < 2; dx++)
                            *(uint32_t*)(out +
                                         (((size_t)b * 256 + 2 * y + dy) * 256 +
                                          2 * x + dx) *
                                             256 +
                                         oc) = u;
                } else if constexpr (LAYER == 2) {
                    v0 = fmaxf(v0 * sb[b * 64 + oc], 0.f);
                    v1 = fmaxf(v1 * sb[b * 64 + oc + 1], 0.f);
                    __half2 hv = __floats2half2_rn(v0, v1);
                    *(uint32_t*)((__half*)outv +
                                 (((size_t)b * 256 + y) * 256 + x) * 128 + oc) =
                        *(uint32_t*)&hv;
                } else {
                    v0 = fmaxf(v0 + sb[oc], 0.f);
                    v1 = fmaxf(v1 + sb[oc + 1], 0.f);
                    __half2 hv = __floats2half2_rn(v0, v1);
                    *(uint32_t*)((__half*)outv +
                                 (((size_t)b * 256 + y) * 256 + x) * 64 + oc) =
                        *(uint32_t*)&hv;
                }
            }
        }
    }
}

// ---------------------------------------------------------------------------
// L4: 64 -> 3 (padded 8) @256^2, +fb2, NCHW fp32 out.
// CTA = 256 px (full row) x 8 oc; 8 warps all-M (32 px each), m16n8k16 N=8.
// ---------------------------------------------------------------------------
__global__ __launch_bounds__(256) void conv_l4(const __half* __restrict__ in,
                                               const uint32_t* __restrict__ gw,
                                               const float* __restrict__ fb2,
                                               float* __restrict__ out) {
    __shared__ uint32_t sA[258][20];
    __shared__ uint32_t sB[3][8][20];

    const int t = threadIdx.x, lane = t & 31, wid = t >> 5;
    const int g = lane >> 2, tig = lane & 3;
    const int y = blockIdx.x, b = blockIdx.y;

    const __half* inb = in + (size_t)b * 256 * 256 * 64;

    float acc[2][4];
#pragma unroll
    for (int mt = 0; mt < 2; mt++)
#pragma unroll
        for (int k = 0; k < 4; k++) acc[mt][k] = 0.f;

    for (int ic0 = 0; ic0 < 64; ic0 += 32) {
        for (int ky = 0; ky < 3; ky++) {
            __syncthreads();
            // B tile: 3kx x 8oc x 16 words = 96 uint4
            if (t < 96) {
                const int q4 = t & 3, oc = (t >> 2) & 7, kx = t >> 5;
                *(uint4*)&sB[kx][oc][q4 * 4] = *(const uint4*)(
                    gw + (size_t)((ky * 3 + kx) * 8 + oc) * 32 + (ic0 >> 1) +
                    q4 * 4);
            }
            // A slab: row y+ky-1, 258 px x 32 ch
            const int gy = y + ky - 1;
            for (int i = t; i < 1032; i += 256) {
                const int px = i >> 2, q = i & 3;
                const int gx = px - 1;
                uint4 u = {0u, 0u, 0u, 0u};
                if (gy >= 0 && gy < 256 && gx >= 0 && gx < 256)
                    u = *(const uint4*)(inb + ((size_t)gy * 256 + gx) * 64 +
                                        ic0 + q * 8);
                *(uint4*)&sA[px][q * 4] = u;
            }
            __syncthreads();
#pragma unroll
            for (int kx = 0; kx < 3; kx++) {
#pragma unroll
                for (int ks = 0; ks < 2; ks++) {
                    const int kb = ks * 8;
                    uint32_t a[2][4];
#pragma unroll
                    for (int mt = 0; mt < 2; mt++) {
                        const int r0 = wid * 32 + mt * 16 + g + kx;
                        a[mt][0] = sA[r0][kb + tig];
                        a[mt][1] = sA[r0 + 8][kb + tig];
                        a[mt][2] = sA[r0][kb + tig + 4];
                        a[mt][3] = sA[r0 + 8][kb + tig + 4];
                    }
                    const uint32_t b0 = sB[kx][g][kb + tig];
                    const uint32_t b1 = sB[kx][g][kb + tig + 4];
                    mma16(acc[0], a[0], b0, b1);
                    mma16(acc[1], a[1], b0, b1);
                }
            }
        }
    }

    const int oc = tig * 2;
#pragma unroll
    for (int mt = 0; mt < 2; mt++) {
#pragma unroll
        for (int h = 0; h < 2; h++) {
            const int x = wid * 32 + mt * 16 + g + h * 8;
            float v0 = acc[mt][h * 2 + 0];
            float v1 = acc[mt][h * 2 + 1];
            if (oc < 3)
                out[(((size_t)b * 3 + oc) * 256 + y) * 256 + x] = v0 + fb2[oc];
            if (oc + 1 < 3)
                out[(((size_t)b * 3 + oc + 1) * 256 + y) * 256 + x] =
                    v1 + fb2[oc + 1];
        }
    }
}

// ---------------------------------------------------------------------------
extern "C" void kernel_launch(void* const* d_in, const int* in_sizes, int n_in,
                              void* d_out, int out_size) {
    const float* x     = (const float*)d_in[0];
    const float* enc1  = (const float*)d_in[1];
    const float* enc2  = (const float*)d_in[2];
    const float* enc3  = (const float*)d_in[3];
    const float* style = (const float*)d_in[4];
    const float* w1    = (const float*)d_in[5];
    const float* fcw1  = (const float*)d_in[6];
    const float* fcb1  = (const float*)d_in[7];
    const float* w2    = (const float*)d_in[8];
    const float* fcw2  = (const float*)d_in[9];
    const float* fcb2  = (const float*)d_in[10];
    const float* fw1   = (const float*)d_in[11];
    const float* fb1   = (const float*)d_in[12];
    const float* fw2   = (const float*)d_in[13];
    const float* fb2   = (const float*)d_in[14];
    float* out = (float*)d_out;

    __half *A1, *A2, *A3, *O3;
    uint32_t *gw1, *gw2, *gw3, *gw4;
    float *s1, *s2;
    cudaGetSymbolAddress((void**)&A1, g_A1);
    cudaGetSymbolAddress((void**)&A2, g_A2);
    cudaGetSymbolAddress((void**)&A3, g_A3);
    cudaGetSymbolAddress((void**)&O3, g_O3);
    cudaGetSymbolAddress((void**)&gw1, g_w1);
    cudaGetSymbolAddress((void**)&gw2, g_w2);
    cudaGetSymbolAddress((void**)&gw3, g_w3);
    cudaGetSymbolAddress((void**)&gw4, g_w4);
    cudaGetSymbolAddress((void**)&s1, g_s1);
    cudaGetSymbolAddress((void**)&s2, g_s2);

    cudaFuncSetAttribute(conv_mma<1>, cudaFuncAttributeMaxDynamicSharedMemorySize, DYN_B);
    cudaFuncSetAttribute(conv_mma<2>, cudaFuncAttributeMaxDynamicSharedMemorySize, DYN_B);
    cudaFuncSetAttribute(conv_mma<3>, cudaFuncAttributeMaxDynamicSharedMemorySize, DYN_B);

    constexpr int NW = 9 * 128 * 256 + 9 * 64 * 128 + 9 * 64 * 64 + 9 * 8 * 32;

    // Launch order keeps conv_mma<1> at index 5 for ncu -s 5 -c 1.
    /*0*/ wtransAll<<<(NW + 255) / 256, 256>>>(w1, w2, fw1, fw2, gw1, gw2, gw3,
                                               gw4);
    /*1*/ styleAll<<<6, 256>>>(style, fcw1, fcb1, fcw2, fcb2, s1, s2);
    /*2*/ nchw2nhwc<true><<<dim3(8, 128, 8), 256>>>(x, A1, 256, 64, 128, 512, 0);
    /*3*/ nchw2nhwc<true><<<dim3(8, 128, 8), 256>>>(enc3, A1, 256, 64, 128, 512,
                                                    256);
    /*4*/ nchw2nhwc<true><<<dim3(8, 256, 8), 256>>>(enc2, A2, 128, 128, 256, 256,
                                                    128);
    /*5*/ conv_mma<1><<<dim3(128, 16), 256, DYN_B>>>(A1, gw1, s1, A2);
    /*6*/ nchw2nhwc<false><<<dim3(4, 256, 8), 256>>>(enc1, A3, 64, 256, 256, 128,
                                                     64);
    /*7*/ conv_mma<2><<<dim3(512, 8), 256, DYN_B>>>(A2, gw2, s2, A3);
    /*8*/ conv_mma<3><<<dim3(512, 8), 256, DYN_B>>>(A3, gw3, fb1, O3);
    /*9*/ conv_l4<<<dim3(256, 8), 256>>>(O3, gw4, fb2, out);
}

// round 17
// speedup vs baseline: 2.7621x; 1.0661x over previous
#include <cuda_runtime.h>
#include <cuda_fp16.h>
#include <cstdint>
#include <cstddef>

// ===========================================================================
// UNet decoder via warp-level fp16 mma.sync (m16n8k16, fp32 accumulate).
// R17: nearest-up2 folded into conv A-loaders (no materialized upsample;
// all activations stored at native resolution), conversions shrink 4x,
// redundant mainloop barrier removed. cp.async double-buffered pipeline.
// ===========================================================================

__device__ __half g_A1[8 * 64 * 64 * 512];    // cat(x,enc3) NHWC @64^2
__device__ __half g_O1[8 * 128 * 128 * 128];  // conv1 out @128^2
__device__ __half g_E2[8 * 128 * 128 * 128];  // enc2 NHWC @128^2
__device__ __half g_A3[8 * 256 * 256 * 128];  // [conv2out | enc1] @256^2
__device__ __half g_O3[8 * 256 * 256 * 64];   // conv3 out
__device__ uint32_t g_w1[9 * 128 * 256];      // [ky][kx][oc][ic2] half2
__device__ uint32_t g_w2[9 * 64 * 128];
__device__ uint32_t g_w3[9 * 64 * 64];
__device__ uint32_t g_w4[9 * 8 * 32];         // L4: oc padded 3 -> 8
__device__ float g_s1[8 * 128];
__device__ float g_s2[8 * 64];

__device__ __forceinline__ void mma16(float* c, const uint32_t* a, uint32_t b0,
                                      uint32_t b1) {
    asm volatile(
        "mma.sync.aligned.m16n8k16.row.col.f32.f16.f16.f32 "
        "{%0,%1,%2,%3}, {%4,%5,%6,%7}, {%8,%9}, {%0,%1,%2,%3};"
        : "+f"(c[0]), "+f"(c[1]), "+f"(c[2]), "+f"(c[3])
        : "r"(a[0]), "r"(a[1]), "r"(a[2]), "r"(a[3]), "r"(b0), "r"(b1));
}

// cp.async 16B with zero-fill when pred is false (src-size = 0).
__device__ __forceinline__ void cp16(uint32_t dst, const void* src, bool pred) {
    asm volatile("cp.async.ca.shared.global [%0], [%1], 16, %2;"
                 :: "r"(dst), "l"(src), "r"(pred ? 16 : 0));
}

// ---------------------------------------------------------------------------
// NCHW fp32 -> NHWC half (no upsample). Tile: 64 ch x 64 px of one row.
// ---------------------------------------------------------------------------
__global__ __launch_bounds__(256) void nchw2nhwc(const float* __restrict__ src,
                                                 __half* __restrict__ dst,
                                                 int Csrc, int Hsrc, int Crow,
                                                 int coff) {
    __shared__ float sm[64][65];
    const int xtiles = Hsrc >> 6;
    const int xt = blockIdx.x % xtiles;
    const int ct = blockIdx.x / xtiles;
    const int y = blockIdx.y, b = blockIdx.z;
    const int t = threadIdx.x;

    const float* sp =
        src + ((size_t)(b * Csrc + ct * 64) * Hsrc + y) * Hsrc + xt * 64;
    for (int i = t; i < 1024; i += 256) {
        int c = i >> 4, q = i & 15;
        float4 v = *(const float4*)(sp + (size_t)c * Hsrc * Hsrc + q * 4);
        sm[c][q * 4 + 0] = v.x;
        sm[c][q * 4 + 1] = v.y;
        sm[c][q * 4 + 2] = v.z;
        sm[c][q * 4 + 3] = v.w;
    }
    __syncthreads();
    __half* dp = dst + (((size_t)b * Hsrc + y) * Hsrc + xt * 64) * Crow + coff +
                 ct * 64;
    for (int i = t; i < 1024; i += 256) {
        int x = i >> 4, cq = i & 15;
        __half2 h0 = __floats2half2_rn(sm[cq * 4 + 0][x], sm[cq * 4 + 1][x]);
        __half2 h1 = __floats2half2_rn(sm[cq * 4 + 2][x], sm[cq * 4 + 3][x]);
        uint2 u;
        u.x = *(uint32_t*)&h0;
        u.y = *(uint32_t*)&h1;
        *(uint2*)(dp + (size_t)x * Crow + cq * 4) = u;
    }
}

// ---------------------------------------------------------------------------
// Weight pack (all 4 layers fused): w[oc][ic][ky][kx] fp32 ->
//   gw[((ky*3+kx)*OCp + oc)*IC2 + ic2] half2, zero-padded oc.
// ---------------------------------------------------------------------------
__device__ __forceinline__ void wemit(const float* __restrict__ w,
                                      uint32_t* __restrict__ gw, int OCsrc,
                                      int OCp, int IC, int i) {
    const int IC2 = IC >> 1;
    int ic2 = i % IC2;
    int r = i / IC2;
    int oc = r % OCp;
    r /= OCp;
    int kx = r % 3, ky = r / 3;
    float v0 = 0.f, v1 = 0.f;
    if (oc < OCsrc) {
        v0 = w[((size_t)(oc * IC + 2 * ic2) * 3 + ky) * 3 + kx];
        v1 = w[((size_t)(oc * IC + 2 * ic2 + 1) * 3 + ky) * 3 + kx];
    }
    __half2 h = __floats2half2_rn(v0, v1);
    gw[i] = *(uint32_t*)&h;
}

__global__ void wtransAll(const float* __restrict__ w1,
                          const float* __restrict__ w2,
                          const float* __restrict__ w3,
                          const float* __restrict__ w4,
                          uint32_t* __restrict__ g1, uint32_t* __restrict__ g2,
                          uint32_t* __restrict__ g3,
                          uint32_t* __restrict__ g4) {
    constexpr int n1 = 9 * 128 * 256, n2 = 9 * 64 * 128, n3 = 9 * 64 * 64,
                  n4 = 9 * 8 * 32;
    int i = blockIdx.x * blockDim.x + threadIdx.x;
    if (i < n1) {
        wemit(w1, g1, 128, 128, 512, i);
    } else if (i < n1 + n2) {
        wemit(w2, g2, 64, 64, 256, i - n1);
    } else if (i < n1 + n2 + n3) {
        wemit(w3, g3, 64, 64, 128, i - n1 - n2);
    } else if (i < n1 + n2 + n3 + n4) {
        wemit(w4, g4, 3, 8, 64, i - n1 - n2 - n3);
    }
}

// ---------------------------------------------------------------------------
// Both style FCs fused.
// ---------------------------------------------------------------------------
__global__ void styleAll(const float* __restrict__ style,
                         const float* __restrict__ fcw1,
                         const float* __restrict__ fcb1,
                         const float* __restrict__ fcw2,
                         const float* __restrict__ fcb2, float* __restrict__ s1,
                         float* __restrict__ s2) {
    int i = blockIdx.x * blockDim.x + threadIdx.x;
    const float* fcw;
    const float* fcb;
    float* s;
    int OC, j;
    if (i < 8 * 128) {
        fcw = fcw1; fcb = fcb1; s = s1; OC = 128; j = i;
    } else if (i < 8 * 128 + 8 * 64) {
        fcw = fcw2; fcb = fcb2; s = s2; OC = 64; j = i - 8 * 128;
    } else {
        return;
    }
    int b = j / OC, o = j - b * OC;
    const float* st = style + b * 256;
    const float* wp = fcw + o * 256;
    float a = fcb[o];
#pragma unroll 4
    for (int k = 0; k < 256; k++) a = fmaf(st[k], wp[k], a);
    s[j] = a;
}

// ---------------------------------------------------------------------------
// Implicit-GEMM conv3x3, fp16 m16n8k16, cp.async double-buffered, with
// nearest-up2 FOLDED into the A loader (source coords >> 1).
// CTA = 128 out-px x 64 oc, 8 warps 4Mx2N, warp tile 32x32.
// LAYER: 1 in A1@64^2 (512ch, fold), out O1@128^2 (scale,relu)
//        2 in O1|E2@128^2 (fold, split 128/128), out A3 ch0-63 (scale,relu)
//        3 in A3@256^2 (no fold), out O3 (+fb1,relu)
// ---------------------------------------------------------------------------
static constexpr int AW = 130 * 20;            // words per A buffer
static constexpr int BW = 3 * 64 * 20;         // words per B buffer
static constexpr int DYN_B = (2 * AW + 2 * BW) * 4;  // 51520 B

template <int LAYER>
__global__ __launch_bounds__(256, 3) void conv_mma(
    const __half* __restrict__ in0, const __half* __restrict__ in1,
    const uint32_t* __restrict__ gw, const float* __restrict__ sb,
    __half* __restrict__ out) {
    constexpr int H = (LAYER == 1) ? 128 : 256;   // OUT dims
    constexpr int W = H;
    constexpr bool FOLD = (LAYER != 3);
    constexpr int Ws = FOLD ? (H / 2) : H;        // src spatial dim
    constexpr int IC = (LAYER == 1) ? 512 : (LAYER == 2) ? 256 : 128;
    constexpr int ICs = (LAYER == 1) ? 512 : 128; // channels per src tensor
    constexpr int SPLIT = (LAYER == 2) ? 128 : IC;
    constexpr int OCp = (LAYER == 1) ? 128 : 64;
    constexpr int OCB = OCp / 64;
    constexpr int OCrow = (LAYER == 2) ? 128 : OCp;  // out row stride (concat)
    constexpr int XB = W / 128;
    constexpr int P = (IC / 32) * 3;  // passes

    extern __shared__ uint32_t dyn[];
    const uint32_t smem32 = (uint32_t)__cvta_generic_to_shared(dyn);

    const int t = threadIdx.x, lane = t & 31, wid = t >> 5;
    const int g = lane >> 2, tig = lane & 3;
    const int wm = wid >> 1, wn = wid & 1;
    const int y = blockIdx.x / XB, x0 = (blockIdx.x % XB) * 128;
    const int b = blockIdx.y / OCB, ob = (blockIdx.y % OCB) * 64;

    const __half* in0b = in0 + (size_t)b * Ws * Ws * ICs;
    const __half* in1b = in1 + (size_t)b * Ws * Ws * ICs;

    auto prefetch = [&](int p, int buf) {
        const int ic0 = (p / 3) * 32;
        const int ky = p - (p / 3) * 3;
        const int gy = y + ky - 1;
        const uint32_t bbase = smem32 + (2 * AW + buf * BW) * 4;
        for (int i = t; i < 768; i += 256) {
            const int q4 = i & 3, oc = (i >> 2) & 63, kx = i >> 8;
            cp16(bbase + (kx * 1280 + oc * 20 + q4 * 4) * 4,
                 gw + (size_t)((ky * 3 + kx) * OCp + ob + oc) * (IC / 2) +
                     (ic0 >> 1) + q4 * 4,
                 true);
        }
        const __half* s;
        int ico;
        if (ic0 < SPLIT) {
            s = in0b; ico = ic0;
        } else {
            s = in1b; ico = ic0 - SPLIT;
        }
        const int sy = FOLD ? (gy >> 1) : gy;
        const uint32_t abase = smem32 + buf * AW * 4;
        const bool yok = (gy >= 0 && gy < H);
        for (int i = t; i < 520; i += 256) {
            const int px = i >> 2, q = i & 3;
            const int gx = x0 - 1 + px;
            const int sx = FOLD ? (gx >> 1) : gx;
            cp16(abase + (px * 20 + q * 4) * 4,
                 s + ((size_t)sy * Ws + sx) * ICs + ico + q * 8,
                 yok && gx >= 0 && gx < W);
        }
        asm volatile("cp.async.commit_group;" ::: "memory");
    };

    float acc[2][4][4];
#pragma unroll
    for (int mt = 0; mt < 2; mt++)
#pragma unroll
        for (int nt = 0; nt < 4; nt++)
#pragma unroll
            for (int k = 0; k < 4; k++) acc[mt][nt][k] = 0.f;

    prefetch(0, 0);
    for (int p = 0; p < P; p++) {
        asm volatile("cp.async.wait_group 0;" ::: "memory");
        __syncthreads();
        if (p + 1 < P) prefetch(p + 1, (p + 1) & 1);
        const uint32_t(*sA)[20] = (const uint32_t(*)[20])(dyn + (p & 1) * AW);
        const uint32_t(*sB)[64][20] =
            (const uint32_t(*)[64][20])(dyn + 2 * AW + (p & 1) * BW);
#pragma unroll
        for (int kx = 0; kx < 3; kx++) {
#pragma unroll
            for (int ks = 0; ks < 2; ks++) {
                const int kb = ks * 8;
                uint32_t a[2][4];
#pragma unroll
                for (int mt = 0; mt < 2; mt++) {
                    const int r0 = wm * 32 + mt * 16 + g + kx;
                    a[mt][0] = sA[r0][kb + tig];
                    a[mt][1] = sA[r0 + 8][kb + tig];
                    a[mt][2] = sA[r0][kb + tig + 4];
                    a[mt][3] = sA[r0 + 8][kb + tig + 4];
                }
#pragma unroll
                for (int nt = 0; nt < 4; nt++) {
                    const int oc = wn * 32 + nt * 8 + g;
                    const uint32_t b0 = sB[kx][oc][kb + tig];
                    const uint32_t b1 = sB[kx][oc][kb + tig + 4];
                    mma16(acc[0][nt], a[0], b0, b1);
                    mma16(acc[1][nt], a[1], b0, b1);
                }
            }
        }
        // NOTE: no trailing barrier — the top-of-iteration barrier already
        // orders buffer reuse (prefetch p+1 writes the buffer last read at
        // p-1, and every thread passed this iteration's barrier after that).
    }

    // ---------------- epilogue ----------------
#pragma unroll
    for (int mt = 0; mt < 2; mt++) {
#pragma unroll
        for (int nt = 0; nt < 4; nt++) {
            const int oc = ob + wn * 32 + nt * 8 + tig * 2;
#pragma unroll
            for (int h = 0; h < 2; h++) {  // c-rows: x and x+8
                const int x = x0 + wm * 32 + mt * 16 + g + h * 8;
                float v0 = acc[mt][nt][h * 2 + 0];
                float v1 = acc[mt][nt][h * 2 + 1];
                if constexpr (LAYER == 3) {
                    v0 = fmaxf(v0 + sb[oc], 0.f);
                    v1 = fmaxf(v1 + sb[oc + 1], 0.f);
                } else {
                    v0 = fmaxf(v0 * sb[b * OCp + oc], 0.f);
                    v1 = fmaxf(v1 * sb[b * OCp + oc + 1], 0.f);
                }
                __half2 hv = __floats2half2_rn(v0, v1);
                *(uint32_t*)(out + (((size_t)b * H + y) * W + x) * OCrow + oc) =
                    *(uint32_t*)&hv;
            }
        }
    }
}

// ---------------------------------------------------------------------------
// L4: 64 -> 3 (padded 8) @256^2, +fb2, NCHW fp32 out.
// CTA = 256 px (full row) x 8 oc; 8 warps all-M, m16n8k16 N=8.
// ---------------------------------------------------------------------------
__global__ __launch_bounds__(256) void conv_l4(const __half* __restrict__ in,
                                               const uint32_t* __restrict__ gw,
                                               const float* __restrict__ fb2,
                                               float* __restrict__ out) {
    __shared__ uint32_t sA[258][20];
    __shared__ uint32_t sB[3][8][20];

    const int t = threadIdx.x, lane = t & 31, wid = t >> 5;
    const int g = lane >> 2, tig = lane & 3;
    const int y = blockIdx.x, b = blockIdx.y;

    const __half* inb = in + (size_t)b * 256 * 256 * 64;

    float acc[2][4];
#pragma unroll
    for (int mt = 0; mt < 2; mt++)
#pragma unroll
        for (int k = 0; k < 4; k++) acc[mt][k] = 0.f;

    for (int ic0 = 0; ic0 < 64; ic0 += 32) {
        for (int ky = 0; ky < 3; ky++) {
            __syncthreads();
            if (t < 96) {
                const int q4 = t & 3, oc = (t >> 2) & 7, kx = t >> 5;
                *(uint4*)&sB[kx][oc][q4 * 4] = *(const uint4*)(
                    gw + (size_t)((ky * 3 + kx) * 8 + oc) * 32 + (ic0 >> 1) +
                    q4 * 4);
            }
            const int gy = y + ky - 1;
            for (int i = t; i < 1032; i += 256) {
                const int px = i >> 2, q = i & 3;
                const int gx = px - 1;
                uint4 u = {0u, 0u, 0u, 0u};
                if (gy >= 0 && gy < 256 && gx >= 0 && gx < 256)
                    u = *(const uint4*)(inb + ((size_t)gy * 256 + gx) * 64 +
                                        ic0 + q * 8);
                *(uint4*)&sA[px][q * 4] = u;
            }
            __syncthreads();
#pragma unroll
            for (int kx = 0; kx < 3; kx++) {
#pragma unroll
                for (int ks = 0; ks < 2; ks++) {
                    const int kb = ks * 8;
                    uint32_t a[2][4];
#pragma unroll
                    for (int mt = 0; mt < 2; mt++) {
                        const int r0 = wid * 32 + mt * 16 + g + kx;
                        a[mt][0] = sA[r0][kb + tig];
                        a[mt][1] = sA[r0 + 8][kb + tig];
                        a[mt][2] = sA[r0][kb + tig + 4];
                        a[mt][3] = sA[r0 + 8][kb + tig + 4];
                    }
                    const uint32_t b0 = sB[kx][g][kb + tig];
                    const uint32_t b1 = sB[kx][g][kb + tig + 4];
                    mma16(acc[0], a[0], b0, b1);
                    mma16(acc[1], a[1], b0, b1);
                }
            }
        }
    }

    const int oc = tig * 2;
#pragma unroll
    for (int mt = 0; mt < 2; mt++) {
#pragma unroll
        for (int h = 0; h < 2; h++) {
            const int x = wid * 32 + mt * 16 + g + h * 8;
            float v0 = acc[mt][h * 2 + 0];
            float v1 = acc[mt][h * 2 + 1];
            if (oc < 3)
                out[(((size_t)b * 3 + oc) * 256 + y) * 256 + x] = v0 + fb2[oc];
            if (oc + 1 < 3)
                out[(((size_t)b * 3 + oc + 1) * 256 + y) * 256 + x] =
                    v1 + fb2[oc + 1];
        }
    }
}

// ---------------------------------------------------------------------------
extern "C" void kernel_launch(void* const* d_in, const int* in_sizes, int n_in,
                              void* d_out, int out_size) {
    const float* x     = (const float*)d_in[0];
    const float* enc1  = (const float*)d_in[1];
    const float* enc2  = (const float*)d_in[2];
    const float* enc3  = (const float*)d_in[3];
    const float* style = (const float*)d_in[4];
    const float* w1    = (const float*)d_in[5];
    const float* fcw1  = (const float*)d_in[6];
    const float* fcb1  = (const float*)d_in[7];
    const float* w2    = (const float*)d_in[8];
    const float* fcw2  = (const float*)d_in[9];
    const float* fcb2  = (const float*)d_in[10];
    const float* fw1   = (const float*)d_in[11];
    const float* fb1   = (const float*)d_in[12];
    const float* fw2   = (const float*)d_in[13];
    const float* fb2   = (const float*)d_in[14];
    float* out = (float*)d_out;

    __half *A1, *O1, *E2, *A3, *O3;
    uint32_t *gw1, *gw2, *gw3, *gw4;
    float *s1, *s2;
    cudaGetSymbolAddress((void**)&A1, g_A1);
    cudaGetSymbolAddress((void**)&O1, g_O1);
    cudaGetSymbolAddress((void**)&E2, g_E2);
    cudaGetSymbolAddress((void**)&A3, g_A3);
    cudaGetSymbolAddress((void**)&O3, g_O3);
    cudaGetSymbolAddress((void**)&gw1, g_w1);
    cudaGetSymbolAddress((void**)&gw2, g_w2);
    cudaGetSymbolAddress((void**)&gw3, g_w3);
    cudaGetSymbolAddress((void**)&gw4, g_w4);
    cudaGetSymbolAddress((void**)&s1, g_s1);
    cudaGetSymbolAddress((void**)&s2, g_s2);

    cudaFuncSetAttribute(conv_mma<1>, cudaFuncAttributeMaxDynamicSharedMemorySize, DYN_B);
    cudaFuncSetAttribute(conv_mma<2>, cudaFuncAttributeMaxDynamicSharedMemorySize, DYN_B);
    cudaFuncSetAttribute(conv_mma<3>, cudaFuncAttributeMaxDynamicSharedMemorySize, DYN_B);

    constexpr int NW = 9 * 128 * 256 + 9 * 64 * 128 + 9 * 64 * 64 + 9 * 8 * 32;

    // Launch order keeps conv_mma<1> at index 5 for ncu -s 5 -c 1.
    /*0*/ wtransAll<<<(NW + 255) / 256, 256>>>(w1, w2, fw1, fw2, gw1, gw2, gw3,
                                               gw4);
    /*1*/ styleAll<<<6, 256>>>(style, fcw1, fcb1, fcw2, fcb2, s1, s2);
    /*2*/ nchw2nhwc<<<dim3(4, 64, 8), 256>>>(x, A1, 256, 64, 512, 0);
    /*3*/ nchw2nhwc<<<dim3(4, 64, 8), 256>>>(enc3, A1, 256, 64, 512, 256);
    /*4*/ nchw2nhwc<<<dim3(4, 128, 8), 256>>>(enc2, E2, 128, 128, 128, 0);
    /*5*/ conv_mma<1><<<dim3(128, 16), 256, DYN_B>>>(A1, A1, gw1, s1, O1);
    /*6*/ nchw2nhwc<<<dim3(4, 256, 8), 256>>>(enc1, A3, 64, 256, 128, 64);
    /*7*/ conv_mma<2><<<dim3(512, 8), 256, DYN_B>>>(O1, E2, gw2, s2, A3);
    /*8*/ conv_mma<3><<<dim3(512, 8), 256, DYN_B>>>(A3, A3, gw3, fb1, O3);
    /*9*/ conv_l4<<<dim3(256, 8), 256>>>(O3, gw4, fb2, out);
}